// round 5
// baseline (speedup 1.0000x reference)
#include <cuda_runtime.h>
#include <cuda_bf16.h>
#include <cstdint>

// ---------------------------------------------------------------------------
// Problem constants (shapes fixed by the dataset)
// ---------------------------------------------------------------------------
#define NMAX 50000
#define EMAX 800000
#define H1 4
#define C1 64
#define F1 (H1 * C1)   // 256
#define C2 64

// ---------------------------------------------------------------------------
// Scratch (static device memory; no allocation anywhere)
// ---------------------------------------------------------------------------
__device__ float    g_h1[(size_t)NMAX * F1];      // layer1 projected features [N,H1*C1]
__device__ float    g_as1[NMAX * H1];
__device__ float    g_ad1[NMAX * H1];
__device__ unsigned g_m1[NMAX * H1];
__device__ float    g_den1[NMAX * H1];
__device__ float    g_e1[(size_t)(EMAX + NMAX) * H1];
__device__ float    g_agg1[(size_t)NMAX * F1];    // layer1 aggregate; becomes x2 after bias+ELU
__device__ float    g_h2[(size_t)NMAX * C2];      // layer2 projected features [N,C2]
__device__ float    g_as2[NMAX];
__device__ float    g_ad2[NMAX];
__device__ unsigned g_m2[NMAX];
__device__ float    g_den2[NMAX];
__device__ float    g_e2[EMAX + NMAX];

// ---------------------------------------------------------------------------
// GEMM: C[M,N] = A[M,K] * B[K,N], row-major fp32.
// 64x64 tile, TK=32, 256 threads, 4x4 micro-tile per thread.
// Requires N % 64 == 0, K % 32 == 0 (true for all calls here). M guarded.
// ---------------------------------------------------------------------------
__global__ __launch_bounds__(256) void gemm_kernel(
    const float* __restrict__ A, const float* __restrict__ B,
    float* __restrict__ C, int M, int N, int K)
{
    const int TM = 64, TN = 64, TK = 32;
    __shared__ float As[32][64 + 4];
    __shared__ float Bs[32][64];

    int bm = blockIdx.y * TM;
    int bn = blockIdx.x * TN;
    int tid = threadIdx.x;
    int tx = tid & 15;          // 0..15 -> 4 cols each
    int ty = tid >> 4;          // 0..15 -> 4 rows each

    float acc[4][4] = {};

    for (int k0 = 0; k0 < K; k0 += TK) {
        // Load A tile: 64x32 floats = 512 float4, 2 per thread. Transposed into As[k][m].
        #pragma unroll
        for (int i = 0; i < 2; ++i) {
            int idx = tid + i * 256;           // float4 index
            int r  = idx >> 3;                 // row in tile (TK/4 = 8 f4 per row)
            int c4 = idx & 7;
            int gr = bm + r;
            float4 v = make_float4(0.f, 0.f, 0.f, 0.f);
            if (gr < M) v = *(const float4*)&A[(size_t)gr * K + k0 + c4 * 4];
            As[c4 * 4 + 0][r] = v.x;
            As[c4 * 4 + 1][r] = v.y;
            As[c4 * 4 + 2][r] = v.z;
            As[c4 * 4 + 3][r] = v.w;
        }
        // Load B tile: 32x64 floats = 512 float4, 2 per thread.
        #pragma unroll
        for (int i = 0; i < 2; ++i) {
            int idx = tid + i * 256;
            int r  = idx >> 4;                 // TN/4 = 16 f4 per row
            int c4 = idx & 15;
            float4 v = *(const float4*)&B[(size_t)(k0 + r) * N + bn + c4 * 4];
            *(float4*)&Bs[r][c4 * 4] = v;
        }
        __syncthreads();

        #pragma unroll
        for (int k = 0; k < TK; ++k) {
            float a[4], b[4];
            #pragma unroll
            for (int i = 0; i < 4; ++i) a[i] = As[k][ty * 4 + i];
            #pragma unroll
            for (int j = 0; j < 4; ++j) b[j] = Bs[k][tx * 4 + j];
            #pragma unroll
            for (int i = 0; i < 4; ++i)
                #pragma unroll
                for (int j = 0; j < 4; ++j) acc[i][j] += a[i] * b[j];
        }
        __syncthreads();
    }

    #pragma unroll
    for (int i = 0; i < 4; ++i) {
        int gr = bm + ty * 4 + i;
        if (gr < M) {
            *(float4*)&C[(size_t)gr * N + bn + tx * 4] =
                make_float4(acc[i][0], acc[i][1], acc[i][2], acc[i][3]);
        }
    }
}

// ---------------------------------------------------------------------------
// Attention scalars: a_s[n,h] = dot(h[n,h,:], att_src[h,:]), a_d likewise.
// One warp per (n,h).
// ---------------------------------------------------------------------------
__global__ __launch_bounds__(256) void att_kernel(
    const float* __restrict__ hfeat, const float* __restrict__ att_s,
    const float* __restrict__ att_d, float* __restrict__ as_out,
    float* __restrict__ ad_out, int Nn, int H, int C)
{
    int w = (blockIdx.x * blockDim.x + threadIdx.x) >> 5;
    int lane = threadIdx.x & 31;
    if (w >= Nn * H) return;
    int n = w / H, hh = w % H;
    const float* row = hfeat + ((size_t)n * H + hh) * C;
    float s = 0.f, d = 0.f;
    for (int c = lane; c < C; c += 32) {
        float v = row[c];
        s += v * att_s[hh * C + c];
        d += v * att_d[hh * C + c];
    }
    #pragma unroll
    for (int o = 16; o; o >>= 1) {
        s += __shfl_down_sync(0xffffffffu, s, o);
        d += __shfl_down_sync(0xffffffffu, d, o);
    }
    if (lane == 0) { as_out[w] = s; ad_out[w] = d; }
}

// monotone uint encoding of float for atomicMax
__device__ __forceinline__ unsigned enc_f32(float f) {
    unsigned k = __float_as_uint(f);
    return (k & 0x80000000u) ? ~k : (k | 0x80000000u);
}
__device__ __forceinline__ float dec_f32(unsigned k) {
    return __uint_as_float((k & 0x80000000u) ? (k & 0x7FFFFFFFu) : ~k);
}

// ---------------------------------------------------------------------------
// Pass A: per-(edge,head) attention logit + segment max over dst.
// Edges E..E+N-1 are synthesized self-loops.
// ---------------------------------------------------------------------------
__global__ __launch_bounds__(256) void edge_logits_kernel(
    const int* __restrict__ ei, const float* __restrict__ as_,
    const float* __restrict__ ad_, float* __restrict__ ebuf,
    unsigned* __restrict__ mseg, int E, int Nn, int H)
{
    long t = (long)blockIdx.x * blockDim.x + threadIdx.x;
    long total = (long)(E + Nn) * H;
    if (t >= total) return;
    int h = (int)(t % H);
    long e = t / H;
    int s, d;
    if (e < E) { s = ei[e]; d = ei[E + e]; } else { s = d = (int)(e - E); }
    float v = as_[s * H + h] + ad_[d * H + h];
    v = v > 0.f ? v : 0.2f * v;                  // leaky_relu slope 0.2
    ebuf[t] = v;
    atomicMax(&mseg[d * H + h], enc_f32(v));
}

// ---------------------------------------------------------------------------
// Pass B: ex = exp(e - m[dst]); denom[dst] += ex
// ---------------------------------------------------------------------------
__global__ __launch_bounds__(256) void edge_exp_kernel(
    const int* __restrict__ ei, float* __restrict__ ebuf,
    const unsigned* __restrict__ mseg, float* __restrict__ den,
    int E, int Nn, int H)
{
    long t = (long)blockIdx.x * blockDim.x + threadIdx.x;
    long total = (long)(E + Nn) * H;
    if (t >= total) return;
    int h = (int)(t % H);
    long e = t / H;
    int d;
    if (e < E) { d = ei[E + e]; } else { d = (int)(e - E); }
    float mv = dec_f32(mseg[d * H + h]);
    float ex = __expf(ebuf[t] - mv);
    ebuf[t] = ex;
    atomicAdd(&den[d * H + h], ex);
}

// ---------------------------------------------------------------------------
// Pass C: out[dst,h,:] += (ex/denom[dst,h]) * h[src,h,:]
// One thread per (edge, head, float4-chunk). C must be multiple of 4.
// ---------------------------------------------------------------------------
__global__ __launch_bounds__(256) void edge_agg_kernel(
    const int* __restrict__ ei, const float* __restrict__ ebuf,
    const float* __restrict__ den, const float* __restrict__ hfeat,
    float* __restrict__ outp, int E, int Nn, int H, int C4)
{
    long t = (long)blockIdx.x * blockDim.x + threadIdx.x;
    long total = (long)(E + Nn) * H * C4;
    if (t >= total) return;
    int q = (int)(t % C4);
    long r = t / C4;
    int h = (int)(r % H);
    long e = r / H;
    int s, d;
    if (e < E) { s = ei[e]; d = ei[E + e]; } else { s = d = (int)(e - E); }
    float alpha = ebuf[e * H + h] / den[d * H + h];
    float4 v = *(const float4*)&hfeat[(((size_t)s * H + h) * C4 + q) * 4];
    float4 w = make_float4(alpha * v.x, alpha * v.y, alpha * v.z, alpha * v.w);
    float* dst = &outp[(((size_t)d * H + h) * C4 + q) * 4];
    asm volatile("red.global.add.v4.f32 [%0], {%1,%2,%3,%4};"
                 :: "l"(dst), "f"(w.x), "f"(w.y), "f"(w.z), "f"(w.w) : "memory");
}

// ---------------------------------------------------------------------------
// Bias + ELU epilogue (in place), feeding layer 2.
// ---------------------------------------------------------------------------
__global__ __launch_bounds__(256) void bias_elu_kernel(
    float* __restrict__ x, const float* __restrict__ b, long n, int cols)
{
    long t = (long)blockIdx.x * blockDim.x + threadIdx.x;
    if (t >= n) return;
    float v = x[t] + b[(int)(t % cols)];
    x[t] = v > 0.f ? v : expm1f(v);
}

// Bias add (final output).
__global__ __launch_bounds__(256) void bias_add_kernel(
    float* __restrict__ x, const float* __restrict__ b, long n, int cols)
{
    long t = (long)blockIdx.x * blockDim.x + threadIdx.x;
    if (t >= n) return;
    x[t] += b[(int)(t % cols)];
}

// ---------------------------------------------------------------------------
// Launch
// ---------------------------------------------------------------------------
extern "C" void kernel_launch(void* const* d_in, const int* in_sizes, int n_in,
                              void* d_out, int out_size)
{
    const float* x    = (const float*)d_in[0];
    const int*   ei   = (const int*)  d_in[1];
    const float* W1   = (const float*)d_in[2];
    const float* aS1  = (const float*)d_in[3];
    const float* aD1  = (const float*)d_in[4];
    const float* b1   = (const float*)d_in[5];
    const float* W2   = (const float*)d_in[6];
    const float* aS2  = (const float*)d_in[7];
    const float* aD2  = (const float*)d_in[8];
    const float* b2   = (const float*)d_in[9];
    float* out = (float*)d_out;

    const int N = in_sizes[0] / 128;   // 50000
    const int E = in_sizes[1] / 2;     // 800000

    // scratch addresses
    float *h1, *as1, *ad1, *den1, *e1, *agg1, *h2, *as2, *ad2, *den2, *e2;
    unsigned *m1, *m2;
    cudaGetSymbolAddress((void**)&h1,   g_h1);
    cudaGetSymbolAddress((void**)&as1,  g_as1);
    cudaGetSymbolAddress((void**)&ad1,  g_ad1);
    cudaGetSymbolAddress((void**)&m1,   g_m1);
    cudaGetSymbolAddress((void**)&den1, g_den1);
    cudaGetSymbolAddress((void**)&e1,   g_e1);
    cudaGetSymbolAddress((void**)&agg1, g_agg1);
    cudaGetSymbolAddress((void**)&h2,   g_h2);
    cudaGetSymbolAddress((void**)&as2,  g_as2);
    cudaGetSymbolAddress((void**)&ad2,  g_ad2);
    cudaGetSymbolAddress((void**)&m2,   g_m2);
    cudaGetSymbolAddress((void**)&den2, g_den2);
    cudaGetSymbolAddress((void**)&e2,   g_e2);

    const long ET = (long)E + N;       // edges incl. self-loops

    // ---------------- Layer 1 ----------------
    cudaMemsetAsync(m1,   0, (size_t)N * H1 * sizeof(unsigned), 0);
    cudaMemsetAsync(den1, 0, (size_t)N * H1 * sizeof(float), 0);
    cudaMemsetAsync(agg1, 0, (size_t)N * F1 * sizeof(float), 0);

    {
        dim3 grid(F1 / 64, (N + 63) / 64);
        gemm_kernel<<<grid, 256>>>(x, W1, h1, N, F1, 128);
    }
    {
        long warps = (long)N * H1;
        long blocks = (warps * 32 + 255) / 256;
        att_kernel<<<(int)blocks, 256>>>(h1, aS1, aD1, as1, ad1, N, H1, C1);
    }
    {
        long total = ET * H1;
        edge_logits_kernel<<<(int)((total + 255) / 256), 256>>>(ei, as1, ad1, e1, m1, E, N, H1);
        edge_exp_kernel<<<(int)((total + 255) / 256), 256>>>(ei, e1, m1, den1, E, N, H1);
        long totalC = ET * H1 * (C1 / 4);
        edge_agg_kernel<<<(int)((totalC + 255) / 256), 256>>>(ei, e1, den1, h1, agg1, E, N, H1, C1 / 4);
    }
    {
        long n = (long)N * F1;
        bias_elu_kernel<<<(int)((n + 255) / 256), 256>>>(agg1, b1, n, F1);
    }

    // ---------------- Layer 2 ----------------
    cudaMemsetAsync(m2,   0, (size_t)N * sizeof(unsigned), 0);
    cudaMemsetAsync(den2, 0, (size_t)N * sizeof(float), 0);
    cudaMemsetAsync(out,  0, (size_t)N * C2 * sizeof(float), 0);

    {
        dim3 grid(C2 / 64, (N + 63) / 64);
        gemm_kernel<<<grid, 256>>>(agg1, W2, h2, N, C2, F1);
    }
    {
        long warps = (long)N;
        long blocks = (warps * 32 + 255) / 256;
        att_kernel<<<(int)blocks, 256>>>(h2, aS2, aD2, as2, ad2, N, 1, C2);
    }
    {
        long total = ET;
        edge_logits_kernel<<<(int)((total + 255) / 256), 256>>>(ei, as2, ad2, e2, m2, E, N, 1);
        edge_exp_kernel<<<(int)((total + 255) / 256), 256>>>(ei, e2, m2, den2, E, N, 1);
        long totalC = ET * (C2 / 4);
        edge_agg_kernel<<<(int)((totalC + 255) / 256), 256>>>(ei, e2, den2, h2, out, E, N, 1, C2 / 4);
    }
    {
        long n = (long)N * C2;
        bias_add_kernel<<<(int)((n + 255) / 256), 256>>>(out, b2, n, C2);
    }
}

// round 6
// speedup vs baseline: 1.8236x; 1.8236x over previous
#include <cuda_runtime.h>
#include <cuda_bf16.h>
#include <cstdint>

// ---------------------------------------------------------------------------
// Problem constants (shapes fixed by the dataset)
// ---------------------------------------------------------------------------
#define NMAX 50000
#define EMAX 800000
#define H1 4
#define C1 64
#define F1 (H1 * C1)   // 256
#define C2 64

// ---------------------------------------------------------------------------
// Scratch (static device memory; no allocation anywhere)
// ---------------------------------------------------------------------------
__device__ float g_h1[(size_t)NMAX * F1];      // layer1 projected features [N,H1*C1]
__device__ float g_as1[NMAX * H1];
__device__ float g_ad1[NMAX * H1];
__device__ float g_agg1[(size_t)NMAX * F1];    // layer1 output (post bias+ELU) = x2
__device__ float g_h2[(size_t)NMAX * C2];      // layer2 projected features [N,C2]
__device__ float g_as2[NMAX];
__device__ float g_ad2[NMAX];
// CSR (built once per launch; shared by both layers)
__device__ int g_deg[NMAX];
__device__ int g_rowptr[NMAX + 1];
__device__ int g_cursor[NMAX];
__device__ int g_csrc[EMAX];

__device__ __forceinline__ float lrelu(float v) { return v > 0.f ? v : 0.2f * v; }

// ---------------------------------------------------------------------------
// GEMM: C[M,N] = A[M,K] * B[K,N], row-major fp32.
// 64x64 tile, TK=32, 256 threads, 4x4 micro-tile per thread.
// ---------------------------------------------------------------------------
__global__ __launch_bounds__(256) void gemm_kernel(
    const float* __restrict__ A, const float* __restrict__ B,
    float* __restrict__ C, int M, int N, int K)
{
    const int TM = 64, TK = 32;
    __shared__ float As[32][64 + 4];
    __shared__ float Bs[32][64];

    int bm = blockIdx.y * TM;
    int bn = blockIdx.x * 64;
    int tid = threadIdx.x;
    int tx = tid & 15;
    int ty = tid >> 4;

    float acc[4][4] = {};

    for (int k0 = 0; k0 < K; k0 += TK) {
        #pragma unroll
        for (int i = 0; i < 2; ++i) {
            int idx = tid + i * 256;
            int r  = idx >> 3;
            int c4 = idx & 7;
            int gr = bm + r;
            float4 v = make_float4(0.f, 0.f, 0.f, 0.f);
            if (gr < M) v = *(const float4*)&A[(size_t)gr * K + k0 + c4 * 4];
            As[c4 * 4 + 0][r] = v.x;
            As[c4 * 4 + 1][r] = v.y;
            As[c4 * 4 + 2][r] = v.z;
            As[c4 * 4 + 3][r] = v.w;
        }
        #pragma unroll
        for (int i = 0; i < 2; ++i) {
            int idx = tid + i * 256;
            int r  = idx >> 4;
            int c4 = idx & 15;
            float4 v = *(const float4*)&B[(size_t)(k0 + r) * N + bn + c4 * 4];
            *(float4*)&Bs[r][c4 * 4] = v;
        }
        __syncthreads();

        #pragma unroll
        for (int k = 0; k < TK; ++k) {
            float a[4], b[4];
            #pragma unroll
            for (int i = 0; i < 4; ++i) a[i] = As[k][ty * 4 + i];
            #pragma unroll
            for (int j = 0; j < 4; ++j) b[j] = Bs[k][tx * 4 + j];
            #pragma unroll
            for (int i = 0; i < 4; ++i)
                #pragma unroll
                for (int j = 0; j < 4; ++j) acc[i][j] += a[i] * b[j];
        }
        __syncthreads();
    }

    #pragma unroll
    for (int i = 0; i < 4; ++i) {
        int gr = bm + ty * 4 + i;
        if (gr < M) {
            *(float4*)&C[(size_t)gr * N + bn + tx * 4] =
                make_float4(acc[i][0], acc[i][1], acc[i][2], acc[i][3]);
        }
    }
}

// ---------------------------------------------------------------------------
// Attention scalars: a_s[n,h] = dot(h[n,h,:], att_src[h,:]), a_d likewise.
// One warp per (n,h).
// ---------------------------------------------------------------------------
__global__ __launch_bounds__(256) void att_kernel(
    const float* __restrict__ hfeat, const float* __restrict__ att_s,
    const float* __restrict__ att_d, float* __restrict__ as_out,
    float* __restrict__ ad_out, int Nn, int H, int C)
{
    int w = (blockIdx.x * blockDim.x + threadIdx.x) >> 5;
    int lane = threadIdx.x & 31;
    if (w >= Nn * H) return;
    int hh = w % H;
    const float* row = hfeat + (size_t)w * C;
    float s = 0.f, d = 0.f;
    for (int c = lane; c < C; c += 32) {
        float v = row[c];
        s += v * att_s[hh * C + c];
        d += v * att_d[hh * C + c];
    }
    #pragma unroll
    for (int o = 16; o; o >>= 1) {
        s += __shfl_down_sync(0xffffffffu, s, o);
        d += __shfl_down_sync(0xffffffffu, d, o);
    }
    if (lane == 0) { as_out[w] = s; ad_out[w] = d; }
}

// ---------------------------------------------------------------------------
// CSR build: histogram over dst, single-block scan, scatter src ids.
// ---------------------------------------------------------------------------
__global__ __launch_bounds__(256) void hist_kernel(
    const int* __restrict__ ei, int* __restrict__ deg, int E)
{
    int t = blockIdx.x * blockDim.x + threadIdx.x;
    if (t < E) atomicAdd(&deg[ei[E + t]], 1);
}

__global__ __launch_bounds__(1024) void scan_kernel(
    const int* __restrict__ deg, int* __restrict__ rowptr,
    int* __restrict__ cursor, int Nn)
{
    __shared__ int part[1024];
    int tid = threadIdx.x;
    int per = (Nn + 1023) / 1024;
    int start = tid * per;
    int sum = 0;
    for (int i = 0; i < per; ++i) {
        int idx = start + i;
        if (idx < Nn) sum += deg[idx];
    }
    part[tid] = sum;
    __syncthreads();
    for (int o = 1; o < 1024; o <<= 1) {
        int v = (tid >= o) ? part[tid - o] : 0;
        __syncthreads();
        part[tid] += v;
        __syncthreads();
    }
    int offset = (tid == 0) ? 0 : part[tid - 1];
    for (int i = 0; i < per; ++i) {
        int idx = start + i;
        if (idx < Nn) {
            rowptr[idx] = offset;
            cursor[idx] = offset;
            offset += deg[idx];
        }
    }
    if (tid == 1023) rowptr[Nn] = part[1023];
}

__global__ __launch_bounds__(256) void scatter_kernel(
    const int* __restrict__ ei, int* __restrict__ cursor,
    int* __restrict__ csrc, int E)
{
    int t = blockIdx.x * blockDim.x + threadIdx.x;
    if (t < E) {
        int d = ei[E + t];
        int p = atomicAdd(&cursor[d], 1);
        csrc[p] = ei[t];
    }
}

// ---------------------------------------------------------------------------
// Fused GAT gather, layer1 (H=4, C=64). One warp per dst node.
// Self-loop synthesized analytically. Bias+ELU fused into the epilogue.
// ---------------------------------------------------------------------------
__global__ __launch_bounds__(256) void gat_gather_h4(
    const int* __restrict__ rowptr, const int* __restrict__ csrc,
    const float* __restrict__ as_, const float* __restrict__ ad_,
    const float* __restrict__ hfeat, const float* __restrict__ bias,
    float* __restrict__ outp, int Nn)
{
    int dst  = (blockIdx.x * blockDim.x + threadIdx.x) >> 5;
    int lane = threadIdx.x & 31;
    if (dst >= Nn) return;

    int beg = rowptr[dst], end = rowptr[dst + 1];
    float4 ad4 = *(const float4*)&ad_[dst * 4];
    float4 asd = *(const float4*)&as_[dst * 4];

    // max phase (self-loop as seed), lanes parallel over edges
    float m0 = lrelu(asd.x + ad4.x);
    float m1 = lrelu(asd.y + ad4.y);
    float m2 = lrelu(asd.z + ad4.z);
    float m3 = lrelu(asd.w + ad4.w);
    for (int j = beg + lane; j < end; j += 32) {
        int s = csrc[j];
        float4 a = *(const float4*)&as_[s * 4];
        m0 = fmaxf(m0, lrelu(a.x + ad4.x));
        m1 = fmaxf(m1, lrelu(a.y + ad4.y));
        m2 = fmaxf(m2, lrelu(a.z + ad4.z));
        m3 = fmaxf(m3, lrelu(a.w + ad4.w));
    }
    #pragma unroll
    for (int o = 16; o; o >>= 1) {
        m0 = fmaxf(m0, __shfl_xor_sync(0xffffffffu, m0, o));
        m1 = fmaxf(m1, __shfl_xor_sync(0xffffffffu, m1, o));
        m2 = fmaxf(m2, __shfl_xor_sync(0xffffffffu, m2, o));
        m3 = fmaxf(m3, __shfl_xor_sync(0xffffffffu, m3, o));
    }

    // accumulation phase: edge-serial, warp-wide coalesced feature loads.
    // Lane covers float4 index `lane` (heads 0/1) and `lane+32` (heads 2/3).
    bool hi = (lane & 16) != 0;      // lane>=16 within each half -> head 1 / head 3
    float4 accA = make_float4(0.f, 0.f, 0.f, 0.f);
    float4 accB = make_float4(0.f, 0.f, 0.f, 0.f);
    float den0 = 0.f, den1 = 0.f, den2 = 0.f, den3 = 0.f;

    // self-loop
    {
        float ex0 = __expf(lrelu(asd.x + ad4.x) - m0);
        float ex1 = __expf(lrelu(asd.y + ad4.y) - m1);
        float ex2 = __expf(lrelu(asd.z + ad4.z) - m2);
        float ex3 = __expf(lrelu(asd.w + ad4.w) - m3);
        den0 += ex0; den1 += ex1; den2 += ex2; den3 += ex3;
        const float4* hp = (const float4*)&hfeat[(size_t)dst * F1];
        float4 vA = hp[lane];
        float4 vB = hp[lane + 32];
        float exA = hi ? ex1 : ex0;
        float exB = hi ? ex3 : ex2;
        accA.x += exA * vA.x; accA.y += exA * vA.y; accA.z += exA * vA.z; accA.w += exA * vA.w;
        accB.x += exB * vB.x; accB.y += exB * vB.y; accB.z += exB * vB.z; accB.w += exB * vB.w;
    }
    for (int j = beg; j < end; ++j) {
        int s = csrc[j];
        float4 a = *(const float4*)&as_[s * 4];
        float ex0 = __expf(lrelu(a.x + ad4.x) - m0);
        float ex1 = __expf(lrelu(a.y + ad4.y) - m1);
        float ex2 = __expf(lrelu(a.z + ad4.z) - m2);
        float ex3 = __expf(lrelu(a.w + ad4.w) - m3);
        den0 += ex0; den1 += ex1; den2 += ex2; den3 += ex3;
        const float4* hp = (const float4*)&hfeat[(size_t)s * F1];
        float4 vA = hp[lane];
        float4 vB = hp[lane + 32];
        float exA = hi ? ex1 : ex0;
        float exB = hi ? ex3 : ex2;
        accA.x += exA * vA.x; accA.y += exA * vA.y; accA.z += exA * vA.z; accA.w += exA * vA.w;
        accB.x += exB * vB.x; accB.y += exB * vB.y; accB.z += exB * vB.z; accB.w += exB * vB.w;
    }

    float denA = hi ? den1 : den0;
    float denB = hi ? den3 : den2;
    float rA = 1.f / denA, rB = 1.f / denB;

    float4 bA = *(const float4*)&bias[lane * 4];
    float4 bB = *(const float4*)&bias[128 + lane * 4];
    float4 oA, oB;
    oA.x = accA.x * rA + bA.x; oA.y = accA.y * rA + bA.y;
    oA.z = accA.z * rA + bA.z; oA.w = accA.w * rA + bA.w;
    oB.x = accB.x * rB + bB.x; oB.y = accB.y * rB + bB.y;
    oB.z = accB.z * rB + bB.z; oB.w = accB.w * rB + bB.w;
    // ELU
    oA.x = oA.x > 0.f ? oA.x : expm1f(oA.x);
    oA.y = oA.y > 0.f ? oA.y : expm1f(oA.y);
    oA.z = oA.z > 0.f ? oA.z : expm1f(oA.z);
    oA.w = oA.w > 0.f ? oA.w : expm1f(oA.w);
    oB.x = oB.x > 0.f ? oB.x : expm1f(oB.x);
    oB.y = oB.y > 0.f ? oB.y : expm1f(oB.y);
    oB.z = oB.z > 0.f ? oB.z : expm1f(oB.z);
    oB.w = oB.w > 0.f ? oB.w : expm1f(oB.w);

    *(float4*)&outp[(size_t)dst * F1 + lane * 4]       = oA;
    *(float4*)&outp[(size_t)dst * F1 + 128 + lane * 4] = oB;
}

// ---------------------------------------------------------------------------
// Fused GAT gather, layer2 (H=1, C=64). One warp per dst. Bias fused.
// ---------------------------------------------------------------------------
__global__ __launch_bounds__(256) void gat_gather_h1(
    const int* __restrict__ rowptr, const int* __restrict__ csrc,
    const float* __restrict__ as_, const float* __restrict__ ad_,
    const float* __restrict__ hfeat, const float* __restrict__ bias,
    float* __restrict__ outp, int Nn)
{
    int dst  = (blockIdx.x * blockDim.x + threadIdx.x) >> 5;
    int lane = threadIdx.x & 31;
    if (dst >= Nn) return;

    int beg = rowptr[dst], end = rowptr[dst + 1];
    float ad = ad_[dst];
    float eself = lrelu(as_[dst] + ad);

    float m = eself;
    for (int j = beg + lane; j < end; j += 32) {
        int s = csrc[j];
        m = fmaxf(m, lrelu(as_[s] + ad));
    }
    #pragma unroll
    for (int o = 16; o; o >>= 1)
        m = fmaxf(m, __shfl_xor_sync(0xffffffffu, m, o));

    float2 acc = make_float2(0.f, 0.f);
    float den = 0.f;
    {
        float ex = __expf(eself - m);
        den += ex;
        float2 v = *(const float2*)&hfeat[(size_t)dst * C2 + lane * 2];
        acc.x += ex * v.x; acc.y += ex * v.y;
    }
    for (int j = beg; j < end; ++j) {
        int s = csrc[j];
        float ex = __expf(lrelu(as_[s] + ad) - m);
        den += ex;
        float2 v = *(const float2*)&hfeat[(size_t)s * C2 + lane * 2];
        acc.x += ex * v.x; acc.y += ex * v.y;
    }
    float r = 1.f / den;
    float2 b = *(const float2*)&bias[lane * 2];
    float2 o = make_float2(acc.x * r + b.x, acc.y * r + b.y);
    *(float2*)&outp[(size_t)dst * C2 + lane * 2] = o;
}

// ---------------------------------------------------------------------------
// Launch
// ---------------------------------------------------------------------------
extern "C" void kernel_launch(void* const* d_in, const int* in_sizes, int n_in,
                              void* d_out, int out_size)
{
    const float* x    = (const float*)d_in[0];
    const int*   ei   = (const int*)  d_in[1];
    const float* W1   = (const float*)d_in[2];
    const float* aS1  = (const float*)d_in[3];
    const float* aD1  = (const float*)d_in[4];
    const float* b1   = (const float*)d_in[5];
    const float* W2   = (const float*)d_in[6];
    const float* aS2  = (const float*)d_in[7];
    const float* aD2  = (const float*)d_in[8];
    const float* b2   = (const float*)d_in[9];
    float* out = (float*)d_out;

    const int N = in_sizes[0] / 128;   // 50000
    const int E = in_sizes[1] / 2;     // 800000

    float *h1, *as1, *ad1, *agg1, *h2, *as2, *ad2;
    int *deg, *rowptr, *cursor, *csrc;
    cudaGetSymbolAddress((void**)&h1,     g_h1);
    cudaGetSymbolAddress((void**)&as1,    g_as1);
    cudaGetSymbolAddress((void**)&ad1,    g_ad1);
    cudaGetSymbolAddress((void**)&agg1,   g_agg1);
    cudaGetSymbolAddress((void**)&h2,     g_h2);
    cudaGetSymbolAddress((void**)&as2,    g_as2);
    cudaGetSymbolAddress((void**)&ad2,    g_ad2);
    cudaGetSymbolAddress((void**)&deg,    g_deg);
    cudaGetSymbolAddress((void**)&rowptr, g_rowptr);
    cudaGetSymbolAddress((void**)&cursor, g_cursor);
    cudaGetSymbolAddress((void**)&csrc,   g_csrc);

    const int WARPS_PER_BLK = 8;                       // 256 threads
    const int gatherBlocks = (N + WARPS_PER_BLK - 1) / WARPS_PER_BLK;

    // -------- CSR build (shared by both layers) --------
    cudaMemsetAsync(deg, 0, (size_t)N * sizeof(int), 0);
    hist_kernel<<<(E + 255) / 256, 256>>>(ei, deg, E);
    scan_kernel<<<1, 1024>>>(deg, rowptr, cursor, N);
    scatter_kernel<<<(E + 255) / 256, 256>>>(ei, cursor, csrc, E);

    // ---------------- Layer 1 ----------------
    {
        dim3 grid(F1 / 64, (N + 63) / 64);
        gemm_kernel<<<grid, 256>>>(x, W1, h1, N, F1, 128);
    }
    {
        long warps = (long)N * H1;
        long blocks = (warps * 32 + 255) / 256;
        att_kernel<<<(int)blocks, 256>>>(h1, aS1, aD1, as1, ad1, N, H1, C1);
    }
    gat_gather_h4<<<gatherBlocks, 256>>>(rowptr, csrc, as1, ad1, h1, b1, agg1, N);

    // ---------------- Layer 2 ----------------
    {
        dim3 grid(C2 / 64, (N + 63) / 64);
        gemm_kernel<<<grid, 256>>>(agg1, W2, h2, N, C2, F1);
    }
    {
        long blocks = ((long)N * 32 + 255) / 256;
        att_kernel<<<(int)blocks, 256>>>(h2, aS2, aD2, as2, ad2, N, 1, C2);
    }
    gat_gather_h1<<<gatherBlocks, 256>>>(rowptr, csrc, as2, ad2, h2, b2, out, N);
}